// round 2
// baseline (speedup 1.0000x reference)
#include <cuda_runtime.h>
#include <cstdint>
#include <math.h>

#define B_  32
#define S_  2048
#define D_  512
#define M_TOTAL (B_ * S_)

// Gate probabilities scratch (device global: allocation-free).
__device__ float g_gate[M_TOTAL];

// ---------------------------------------------------------------------------
// helpers
// ---------------------------------------------------------------------------
__device__ __forceinline__ uint32_t f2tf32(float f) {
    uint32_t u;
    asm("cvt.rna.tf32.f32 %0, %1;" : "=r"(u) : "f"(f));
    return u;
}

__device__ __forceinline__ void mma_tf32(float* c, const uint32_t* a, const uint32_t* b) {
    asm volatile(
        "mma.sync.aligned.m16n8k8.row.col.f32.tf32.tf32.f32 "
        "{%0,%1,%2,%3}, {%4,%5,%6,%7}, {%8,%9}, {%0,%1,%2,%3};"
        : "+f"(c[0]), "+f"(c[1]), "+f"(c[2]), "+f"(c[3])
        : "r"(a[0]), "r"(a[1]), "r"(a[2]), "r"(a[3]), "r"(b[0]), "r"(b[1]));
}

// XOR swizzle for a [128][32] fp32 tile: bank-conflict-free column reads,
// preserves float4 (16B) store alignment since XOR operand is a multiple of 4.
__device__ __forceinline__ int swz(int row, int col) {
    return row * 32 + (col ^ ((row & 7) << 2));
}

// Load a 128x32 fp32 tile (rows stride D_ in gmem) into swizzled smem.
__device__ __forceinline__ void load_tile(float* sm, const float* __restrict__ gp,
                                          int row0, int k0, int tid) {
    #pragma unroll
    for (int i = tid; i < 128 * 8; i += 256) {
        int r  = i >> 3;
        int c4 = (i & 7) << 2;
        float4 v = *reinterpret_cast<const float4*>(gp + (size_t)(row0 + r) * D_ + k0 + c4);
        *reinterpret_cast<float4*>(sm + swz(r, c4)) = v;
    }
}

// ---------------------------------------------------------------------------
// Kernel 1: gate path.
//   h = relu(old_x @ W1^T + b1) + old_x ; logit = h . W2 + b2 ; g = sigmoid
// One CTA per 128-row tile (each tile is within a single batch -> single lang).
// ---------------------------------------------------------------------------
__global__ void __launch_bounds__(256) k1_gate(
    const float* __restrict__ old_x, const int* __restrict__ lang,
    const float* __restrict__ gW1,  const float* __restrict__ gb1,
    const float* __restrict__ gW2,  const float* __restrict__ gb2)
{
    __shared__ float xs[128 * 32];
    __shared__ float ws[128 * 32];
    __shared__ float logits[128];

    const int rt   = blockIdx.x;
    const int row0 = rt * 128;
    const int bb   = row0 / S_;
    const int lg   = lang[bb];

    const float* W1l = gW1 + (size_t)lg * D_ * D_;
    const float* b1l = gb1 + lg * D_;
    const float* W2l = gW2 + lg * D_;

    const int tid  = threadIdx.x;
    const int wid  = tid >> 5, lane = tid & 31;
    const int wm   = wid & 3,  wn   = wid >> 2;   // 4x2 warp grid
    const int g    = lane >> 2, t   = lane & 3;

    if (tid < 128) logits[tid] = 0.f;

    for (int nt = 0; nt < 4; nt++) {
        const int n0 = nt * 128;
        float c[2][8][4];
        #pragma unroll
        for (int mi = 0; mi < 2; mi++)
            #pragma unroll
            for (int ni = 0; ni < 8; ni++)
                #pragma unroll
                for (int r = 0; r < 4; r++) c[mi][ni][r] = 0.f;

        for (int kt = 0; kt < D_; kt += 32) {
            __syncthreads();
            load_tile(xs, old_x, row0, kt, tid);
            load_tile(ws, W1l,   n0,   kt, tid);
            __syncthreads();
            #pragma unroll
            for (int kk = 0; kk < 32; kk += 8) {
                uint32_t a[2][4];
                #pragma unroll
                for (int mi = 0; mi < 2; mi++) {
                    int mr = wm * 32 + mi * 16 + g;
                    a[mi][0] = f2tf32(xs[swz(mr,     kk + t)]);
                    a[mi][1] = f2tf32(xs[swz(mr + 8, kk + t)]);
                    a[mi][2] = f2tf32(xs[swz(mr,     kk + t + 4)]);
                    a[mi][3] = f2tf32(xs[swz(mr + 8, kk + t + 4)]);
                }
                #pragma unroll
                for (int ni = 0; ni < 8; ni++) {
                    int nr = wn * 64 + ni * 8 + g;
                    uint32_t bf[2];
                    bf[0] = f2tf32(ws[swz(nr, kk + t)]);
                    bf[1] = f2tf32(ws[swz(nr, kk + t + 4)]);
                    mma_tf32(c[0][ni], a[0], bf);
                    mma_tf32(c[1][ni], a[1], bf);
                }
            }
        }

        // Fused epilogue: relu(+b1) + old_x, dot with W2, reduce into logits.
        float part[2][2] = {{0.f, 0.f}, {0.f, 0.f}};
        #pragma unroll
        for (int ni = 0; ni < 8; ni++) {
            int e0 = n0 + wn * 64 + ni * 8 + 2 * t;
            float b1a = b1l[e0], b1b = b1l[e0 + 1];
            float w2a = W2l[e0], w2b = W2l[e0 + 1];
            #pragma unroll
            for (int mi = 0; mi < 2; mi++) {
                int mrow = row0 + wm * 32 + mi * 16 + g;
                const float* ox0 = old_x + (size_t)mrow * D_;
                const float* ox1 = ox0 + 8 * D_;
                float v0 = fmaxf(c[mi][ni][0] + b1a, 0.f) + ox0[e0];
                float v1 = fmaxf(c[mi][ni][1] + b1b, 0.f) + ox0[e0 + 1];
                float v2 = fmaxf(c[mi][ni][2] + b1a, 0.f) + ox1[e0];
                float v3 = fmaxf(c[mi][ni][3] + b1b, 0.f) + ox1[e0 + 1];
                part[mi][0] += v0 * w2a + v1 * w2b;
                part[mi][1] += v2 * w2a + v3 * w2b;
            }
        }
        int mloc = wm * 32 + g;
        atomicAdd(&logits[mloc],      part[0][0]);
        atomicAdd(&logits[mloc + 8],  part[0][1]);
        atomicAdd(&logits[mloc + 16], part[1][0]);
        atomicAdd(&logits[mloc + 24], part[1][1]);
    }

    __syncthreads();
    if (tid < 128) {
        float z = logits[tid] + gb2[lg];
        g_gate[row0 + tid] = 1.f / (1.f + expf(-z));
    }
}

// ---------------------------------------------------------------------------
// Kernel 2: dual-GEMM mix.
//   out = (x@Ws^T) * (1-g) + (x@Wl^T) * g
// One CTA per 128x128 output tile; both GEMMs share A fragments and K loop.
// ---------------------------------------------------------------------------
__global__ void __launch_bounds__(256) k2_mix(
    const float* __restrict__ x,     const int* __restrict__ lang,
    const float* __restrict__ shareW, const float* __restrict__ langsW,
    float* __restrict__ out)
{
    __shared__ float xs[128 * 32];
    __shared__ float wss[128 * 32];
    __shared__ float wsl[128 * 32];

    const int rt   = blockIdx.x;      // 512 row tiles
    const int nt   = blockIdx.y;      // 4 col tiles
    const int row0 = rt * 128;
    const int n0   = nt * 128;
    const int bb   = row0 / S_;
    const int lg   = lang[bb];
    const float* Wl = langsW + (size_t)lg * D_ * D_;

    const int tid  = threadIdx.x;
    const int wid  = tid >> 5, lane = tid & 31;
    const int wm   = wid & 3,  wn   = wid >> 2;   // 4x2 warp grid
    const int g    = lane >> 2, t   = lane & 3;

    float cs[2][8][4], cl[2][8][4];
    #pragma unroll
    for (int mi = 0; mi < 2; mi++)
        #pragma unroll
        for (int ni = 0; ni < 8; ni++)
            #pragma unroll
            for (int r = 0; r < 4; r++) { cs[mi][ni][r] = 0.f; cl[mi][ni][r] = 0.f; }

    for (int kt = 0; kt < D_; kt += 32) {
        __syncthreads();
        load_tile(xs,  x,      row0, kt, tid);
        load_tile(wss, shareW, n0,   kt, tid);
        load_tile(wsl, Wl,     n0,   kt, tid);
        __syncthreads();
        #pragma unroll
        for (int kk = 0; kk < 32; kk += 8) {
            uint32_t a[2][4];
            #pragma unroll
            for (int mi = 0; mi < 2; mi++) {
                int mr = wm * 32 + mi * 16 + g;
                a[mi][0] = f2tf32(xs[swz(mr,     kk + t)]);
                a[mi][1] = f2tf32(xs[swz(mr + 8, kk + t)]);
                a[mi][2] = f2tf32(xs[swz(mr,     kk + t + 4)]);
                a[mi][3] = f2tf32(xs[swz(mr + 8, kk + t + 4)]);
            }
            #pragma unroll
            for (int ni = 0; ni < 8; ni++) {
                int nr = wn * 64 + ni * 8 + g;
                uint32_t bs[2], bl[2];
                bs[0] = f2tf32(wss[swz(nr, kk + t)]);
                bs[1] = f2tf32(wss[swz(nr, kk + t + 4)]);
                bl[0] = f2tf32(wsl[swz(nr, kk + t)]);
                bl[1] = f2tf32(wsl[swz(nr, kk + t + 4)]);
                mma_tf32(cs[0][ni], a[0], bs);
                mma_tf32(cs[1][ni], a[1], bs);
                mma_tf32(cl[0][ni], a[0], bl);
                mma_tf32(cl[1][ni], a[1], bl);
            }
        }
    }

    // Epilogue: blend with gate and store.
    #pragma unroll
    for (int mi = 0; mi < 2; mi++) {
        int mbase = wm * 32 + mi * 16 + g;
        float g0 = g_gate[row0 + mbase];
        float g1 = g_gate[row0 + mbase + 8];
        float* o0 = out + (size_t)(row0 + mbase) * D_;
        float* o1 = o0 + 8 * D_;
        #pragma unroll
        for (int ni = 0; ni < 8; ni++) {
            int nb = n0 + wn * 64 + ni * 8 + 2 * t;
            float2 v0, v1;
            v0.x = cs[mi][ni][0] * (1.f - g0) + cl[mi][ni][0] * g0;
            v0.y = cs[mi][ni][1] * (1.f - g0) + cl[mi][ni][1] * g0;
            v1.x = cs[mi][ni][2] * (1.f - g1) + cl[mi][ni][2] * g1;
            v1.y = cs[mi][ni][3] * (1.f - g1) + cl[mi][ni][3] * g1;
            *reinterpret_cast<float2*>(o0 + nb) = v0;
            *reinterpret_cast<float2*>(o1 + nb) = v1;
        }
    }
}

// ---------------------------------------------------------------------------
// launch
// ---------------------------------------------------------------------------
extern "C" void kernel_launch(void* const* d_in, const int* in_sizes, int n_in,
                              void* d_out, int out_size)
{
    const float* old_x  = (const float*)d_in[0];
    const float* x      = (const float*)d_in[1];
    const int*   lang   = (const int*)  d_in[2];
    const float* shareW = (const float*)d_in[3];
    const float* langsW = (const float*)d_in[4];
    const float* gW1    = (const float*)d_in[5];
    const float* gb1    = (const float*)d_in[6];
    const float* gW2    = (const float*)d_in[7];
    const float* gb2    = (const float*)d_in[8];
    float* out = (float*)d_out;

    k1_gate<<<M_TOTAL / 128, 256>>>(old_x, lang, gW1, gb1, gW2, gb2);
    k2_mix<<<dim3(M_TOTAL / 128, D_ / 128), 256>>>(x, lang, shareW, langsW, out);
}

// round 4
// speedup vs baseline: 1.0927x; 1.0927x over previous
#include <cuda_runtime.h>
#include <cstdint>
#include <math.h>

#define B_  32
#define S_  2048
#define D_  512
#define M_TOTAL (B_ * S_)

// Gate probabilities scratch (device global: allocation-free).
__device__ float g_gate[M_TOTAL];

// ---------------------------------------------------------------------------
// helpers
// ---------------------------------------------------------------------------
__device__ __forceinline__ uint32_t smem_u32(const void* p) {
    uint32_t a;
    asm("{ .reg .u64 t; cvta.to.shared.u64 t, %1; cvt.u32.u64 %0, t; }" : "=r"(a) : "l"(p));
    return a;
}
__device__ __forceinline__ uint32_t f2tf32(float f) {
    uint32_t u; asm("cvt.rna.tf32.f32 %0, %1;" : "=r"(u) : "f"(f)); return u;
}
__device__ __forceinline__ void mma_tf32(float* c, const uint32_t* a, uint32_t b0, uint32_t b1) {
    asm volatile(
        "mma.sync.aligned.m16n8k8.row.col.f32.tf32.tf32.f32 "
        "{%0,%1,%2,%3}, {%4,%5,%6,%7}, {%8,%9}, {%0,%1,%2,%3};"
        : "+f"(c[0]), "+f"(c[1]), "+f"(c[2]), "+f"(c[3])
        : "r"(a[0]), "r"(a[1]), "r"(a[2]), "r"(a[3]), "r"(b0), "r"(b1));
}
__device__ __forceinline__ void lds64(uint32_t a, uint32_t& x, uint32_t& y) {
    asm volatile("ld.shared.v2.b32 {%0,%1}, [%2];" : "=r"(x), "=r"(y) : "r"(a));
}
__device__ __forceinline__ void sts128(uint32_t a, uint32_t x, uint32_t y, uint32_t z, uint32_t w) {
    asm volatile("st.shared.v4.b32 [%0], {%1,%2,%3,%4};"
                 :: "r"(a), "r"(x), "r"(y), "r"(z), "r"(w) : "memory");
}

// One "cell" = 32 bytes of a 128x32 tile: row r (0..127), 8-col group grp (0..3).
struct Cell { float4 lo, hi; };

__device__ __forceinline__ Cell ldCell(const float* __restrict__ gp, int r, int grp) {
    Cell c;
    const float4* p = reinterpret_cast<const float4*>(gp + (size_t)r * D_ + grp * 8);
    c.lo = __ldg(p); c.hi = __ldg(p + 1);
    return c;
}

// Store cell into smem with:
//  - tf32 conversion (done once here, not in the MMA loop)
//  - k-permutation within each 8-group: col c -> pos 2*(c&3)+(c>>2),
//    so fragment cols (t, t+4) are adjacent -> LDS.64 fragment loads
//  - XOR swizzle (row&7)<<2 on the 32-float row for bank spreading
__device__ __forceinline__ void stCell(uint32_t tile, int r, int grp, const Cell& c) {
    uint32_t swz  = (uint32_t)((r & 7) << 2);
    uint32_t base = tile + (uint32_t)(r * 128);
    uint32_t p0 = (((uint32_t)(grp * 8))     ^ swz) * 4u;
    uint32_t p1 = (((uint32_t)(grp * 8 + 4)) ^ swz) * 4u;
    // logical positions grp*8+0..3 hold cols {0,4,1,5}; +4..7 hold {2,6,3,7}
    sts128(base + p0, f2tf32(c.lo.x), f2tf32(c.hi.x), f2tf32(c.lo.y), f2tf32(c.hi.y));
    sts128(base + p1, f2tf32(c.lo.z), f2tf32(c.hi.z), f2tf32(c.lo.w), f2tf32(c.hi.w));
}

// ---------------------------------------------------------------------------
// Kernel 1: gate path.
//   h = relu(old_x @ W1^T + b1) + old_x ; logit = h . W2 + b2 ; g = sigmoid
// 512 threads, warp tile 32x32, N looped over 4 tiles, double-buffered smem.
// ---------------------------------------------------------------------------
#define K1_STAGE 32768
#define K1_SMEM  (K1_STAGE * 2 + 512)

__global__ void __launch_bounds__(512, 1) k1_gate(
    const float* __restrict__ old_x, const int* __restrict__ lang,
    const float* __restrict__ gW1,  const float* __restrict__ gb1,
    const float* __restrict__ gW2,  const float* __restrict__ gb2)
{
    extern __shared__ __align__(16) char dsm[];
    const uint32_t sb = smem_u32(dsm);
    const uint32_t A0 = sb, B0 = sb + 16384;
    float* logits = reinterpret_cast<float*>(dsm + K1_STAGE * 2);

    const int tid  = threadIdx.x;
    const int wid  = tid >> 5, lane = tid & 31;
    const int g    = lane >> 2, t = lane & 3;
    const int wm   = wid & 3,  wn  = wid >> 2;       // 4x4 warp grid
    const int cr   = tid >> 2, cg  = tid & 3;        // cell coords

    const int rt   = blockIdx.x;
    const int row0 = rt * 128;
    const int lg   = lang[rt >> 4];

    const float* W1l = gW1 + (size_t)lg * D_ * D_;
    const float* b1l = gb1 + lg * D_;
    const float* W2l = gW2 + lg * D_;
    const float* oxA = old_x + (size_t)row0 * D_;

    if (tid < 128) logits[tid] = 0.f;

    const uint32_t aB  = A0 + (uint32_t)((wm * 32 + g) * 128);
    const uint32_t bB  = B0 + (uint32_t)((wn * 32 + g) * 128);

    float part[2][2] = {{0.f, 0.f}, {0.f, 0.f}};

    for (int nt = 0; nt < 4; nt++) {
        const float* pB = W1l + (size_t)(nt * 128) * D_;
        float cc[2][4][4];
        #pragma unroll
        for (int mi = 0; mi < 2; mi++)
            #pragma unroll
            for (int ni = 0; ni < 4; ni++)
                #pragma unroll
                for (int r = 0; r < 4; r++) cc[mi][ni][r] = 0.f;

        Cell ca = ldCell(oxA, cr, cg);
        Cell cb = ldCell(pB,  cr, cg);
        __syncthreads();                       // stages free (prev nt done)
        stCell(A0, cr, cg, ca);
        stCell(B0, cr, cg, cb);
        __syncthreads();

        #pragma unroll 1
        for (int c = 0; c < 16; c++) {
            const uint32_t so = (uint32_t)(c & 1) * K1_STAGE;
            if (c < 15) {
                int k0 = (c + 1) * 32;
                ca = ldCell(oxA + k0, cr, cg);
                cb = ldCell(pB  + k0, cr, cg);
            }
            #pragma unroll
            for (int kk = 0; kk < 4; kk++) {
                const uint32_t co = (uint32_t)(((kk * 8 + 2 * t) ^ (g << 2)) * 4);
                uint32_t a[2][4];
                lds64(aB + so + co,        a[0][0], a[0][2]);
                lds64(aB + so + 1024 + co, a[0][1], a[0][3]);
                lds64(aB + so + 2048 + co, a[1][0], a[1][2]);
                lds64(aB + so + 3072 + co, a[1][1], a[1][3]);
                #pragma unroll
                for (int ni = 0; ni < 4; ni++) {
                    uint32_t b0, b1;
                    lds64(bB + so + (uint32_t)(ni * 1024) + co, b0, b1);
                    mma_tf32(cc[0][ni], a[0], b0, b1);
                    mma_tf32(cc[1][ni], a[1], b0, b1);
                }
            }
            __syncthreads();
            if (c < 15) {
                const uint32_t so2 = (uint32_t)((c + 1) & 1) * K1_STAGE;
                stCell(A0 + so2, cr, cg, ca);
                stCell(B0 + so2, cr, cg, cb);
                __syncthreads();
            }
        }

        // Fused epilogue: relu(+b1) + old_x, dot W2, accumulate per-row partials.
        #pragma unroll
        for (int mi = 0; mi < 2; mi++) {
            #pragma unroll
            for (int h = 0; h < 2; h++) {
                const int r    = wm * 32 + mi * 16 + h * 8 + g;
                const int grow = row0 + r;
                const float* oxr = old_x + (size_t)grow * D_;
                float acc = 0.f;
                #pragma unroll
                for (int ni = 0; ni < 4; ni++) {
                    const int e = nt * 128 + wn * 32 + ni * 8 + 2 * t;
                    float2 b1v = *reinterpret_cast<const float2*>(b1l + e);
                    float2 w2v = *reinterpret_cast<const float2*>(W2l + e);
                    float2 oxv = *reinterpret_cast<const float2*>(oxr + e);
                    float u0 = fmaxf(cc[mi][ni][2 * h]     + b1v.x, 0.f) + oxv.x;
                    float u1 = fmaxf(cc[mi][ni][2 * h + 1] + b1v.y, 0.f) + oxv.y;
                    acc += u0 * w2v.x + u1 * w2v.y;
                }
                part[mi][h] += acc;
            }
        }
    }

    #pragma unroll
    for (int mi = 0; mi < 2; mi++)
        #pragma unroll
        for (int h = 0; h < 2; h++)
            atomicAdd(&logits[wm * 32 + mi * 16 + h * 8 + g], part[mi][h]);

    __syncthreads();
    if (tid < 128) {
        float z = logits[tid] + gb2[lg];
        g_gate[row0 + tid] = 1.f / (1.f + expf(-z));
    }
}

// ---------------------------------------------------------------------------
// Kernel 2: dual-GEMM mix.
//   out = (x@Ws^T) * (1-g) + (x@Wl^T) * g
// 512 threads, warp tile 32x32 per GEMM, shared A fragments, one K loop.
// Grid: (nt fast, rt slow) so 4 co-resident CTAs share each x slab via L2.
// ---------------------------------------------------------------------------
#define K2_STAGE 49152
#define K2_SMEM  (K2_STAGE * 2)

__global__ void __launch_bounds__(512, 1) k2_mix(
    const float* __restrict__ x,      const int* __restrict__ lang,
    const float* __restrict__ shareW, const float* __restrict__ langsW,
    float* __restrict__ out)
{
    extern __shared__ __align__(16) char dsm[];
    const uint32_t sb = smem_u32(dsm);
    const uint32_t A0 = sb, BS0 = sb + 16384, BL0 = sb + 32768;

    const int tid  = threadIdx.x;
    const int wid  = tid >> 5, lane = tid & 31;
    const int g    = lane >> 2, t = lane & 3;
    const int wm   = wid & 3,  wn  = wid >> 2;
    const int cr   = tid >> 2, cg  = tid & 3;

    const int nt   = blockIdx.x;           // fast: 4 CTAs share one x slab
    const int rt   = blockIdx.y;
    const int row0 = rt * 128;
    const int n0   = nt * 128;
    const int lg   = lang[rt >> 4];

    const float* xA = x + (size_t)row0 * D_;
    const float* pS = shareW + (size_t)n0 * D_;
    const float* pL = langsW + (size_t)lg * D_ * D_ + (size_t)n0 * D_;

    float cs[2][4][4], cl[2][4][4];
    #pragma unroll
    for (int mi = 0; mi < 2; mi++)
        #pragma unroll
        for (int ni = 0; ni < 4; ni++)
            #pragma unroll
            for (int r = 0; r < 4; r++) { cs[mi][ni][r] = 0.f; cl[mi][ni][r] = 0.f; }

    Cell ca = ldCell(xA, cr, cg);
    Cell cS = ldCell(pS, cr, cg);
    Cell cL = ldCell(pL, cr, cg);
    stCell(A0,  cr, cg, ca);
    stCell(BS0, cr, cg, cS);
    stCell(BL0, cr, cg, cL);
    __syncthreads();

    const uint32_t aB  = A0  + (uint32_t)((wm * 32 + g) * 128);
    const uint32_t bSB = BS0 + (uint32_t)((wn * 32 + g) * 128);
    const uint32_t bLB = BL0 + (uint32_t)((wn * 32 + g) * 128);

    #pragma unroll 1
    for (int c = 0; c < 16; c++) {
        const uint32_t so = (uint32_t)(c & 1) * K2_STAGE;
        if (c < 15) {
            int k0 = (c + 1) * 32;
            ca = ldCell(xA + k0, cr, cg);
            cS = ldCell(pS + k0, cr, cg);
            cL = ldCell(pL + k0, cr, cg);
        }
        #pragma unroll
        for (int kk = 0; kk < 4; kk++) {
            const uint32_t co = (uint32_t)(((kk * 8 + 2 * t) ^ (g << 2)) * 4);
            uint32_t a[2][4];
            lds64(aB + so + co,        a[0][0], a[0][2]);
            lds64(aB + so + 1024 + co, a[0][1], a[0][3]);
            lds64(aB + so + 2048 + co, a[1][0], a[1][2]);
            lds64(aB + so + 3072 + co, a[1][1], a[1][3]);
            #pragma unroll
            for (int ni = 0; ni < 4; ni++) {
                uint32_t s0, s1, l0, l1;
                lds64(bSB + so + (uint32_t)(ni * 1024) + co, s0, s1);
                lds64(bLB + so + (uint32_t)(ni * 1024) + co, l0, l1);
                mma_tf32(cs[0][ni], a[0], s0, s1);
                mma_tf32(cs[1][ni], a[1], s0, s1);
                mma_tf32(cl[0][ni], a[0], l0, l1);
                mma_tf32(cl[1][ni], a[1], l0, l1);
            }
        }
        __syncthreads();
        if (c < 15) {
            const uint32_t so2 = (uint32_t)((c + 1) & 1) * K2_STAGE;
            stCell(A0  + so2, cr, cg, ca);
            stCell(BS0 + so2, cr, cg, cS);
            stCell(BL0 + so2, cr, cg, cL);
            __syncthreads();
        }
    }

    // Epilogue: blend with gate, float2 stores.
    #pragma unroll
    for (int mi = 0; mi < 2; mi++) {
        #pragma unroll
        for (int h = 0; h < 2; h++) {
            const int r    = wm * 32 + mi * 16 + h * 8 + g;
            const int grow = row0 + r;
            const float gv  = g_gate[grow];
            const float ngv = 1.f - gv;
            float* orow = out + (size_t)grow * D_ + n0 + wn * 32;
            #pragma unroll
            for (int ni = 0; ni < 4; ni++) {
                float2 v;
                v.x = cs[mi][ni][2 * h]     * ngv + cl[mi][ni][2 * h]     * gv;
                v.y = cs[mi][ni][2 * h + 1] * ngv + cl[mi][ni][2 * h + 1] * gv;
                *reinterpret_cast<float2*>(orow + ni * 8 + 2 * t) = v;
            }
        }
    }
}

// ---------------------------------------------------------------------------
// launch
// ---------------------------------------------------------------------------
extern "C" void kernel_launch(void* const* d_in, const int* in_sizes, int n_in,
                              void* d_out, int out_size)
{
    const float* old_x  = (const float*)d_in[0];
    const float* x      = (const float*)d_in[1];
    const int*   lang   = (const int*)  d_in[2];
    const float* shareW = (const float*)d_in[3];
    const float* langsW = (const float*)d_in[4];
    const float* gW1    = (const float*)d_in[5];
    const float* gb1    = (const float*)d_in[6];
    const float* gW2    = (const float*)d_in[7];
    const float* gb2    = (const float*)d_in[8];
    float* out = (float*)d_out;

    static bool attr_set = false;
    cudaFuncSetAttribute(k1_gate, cudaFuncAttributeMaxDynamicSharedMemorySize, K1_SMEM);
    cudaFuncSetAttribute(k2_mix,  cudaFuncAttributeMaxDynamicSharedMemorySize, K2_SMEM);
    (void)attr_set;

    k1_gate<<<M_TOTAL / 128, 512, K1_SMEM>>>(old_x, lang, gW1, gb1, gW2, gb2);
    k2_mix<<<dim3(D_ / 128, M_TOTAL / 128), 512, K2_SMEM>>>(x, lang, shareW, langsW, out);
}

// round 5
// speedup vs baseline: 1.2637x; 1.1565x over previous
#include <cuda_runtime.h>
#include <cstdint>
#include <math.h>

#define B_  32
#define S_  2048
#define D_  512
#define M_TOTAL (B_ * S_)

// Gate probabilities scratch (device global: allocation-free).
__device__ float g_gate[M_TOTAL];

// ---------------------------------------------------------------------------
// helpers
// ---------------------------------------------------------------------------
__device__ __forceinline__ uint32_t smem_u32(const void* p) {
    uint32_t a;
    asm("{ .reg .u64 t; cvta.to.shared.u64 t, %1; cvt.u32.u64 %0, t; }" : "=r"(a) : "l"(p));
    return a;
}
__device__ __forceinline__ uint32_t f2tf32(float f) {
    uint32_t u; asm("cvt.rna.tf32.f32 %0, %1;" : "=r"(u) : "f"(f)); return u;
}
__device__ __forceinline__ void mma_tf32(float* c, const uint32_t* a, uint32_t b0, uint32_t b1) {
    asm volatile(
        "mma.sync.aligned.m16n8k8.row.col.f32.tf32.tf32.f32 "
        "{%0,%1,%2,%3}, {%4,%5,%6,%7}, {%8,%9}, {%0,%1,%2,%3};"
        : "+f"(c[0]), "+f"(c[1]), "+f"(c[2]), "+f"(c[3])
        : "r"(a[0]), "r"(a[1]), "r"(a[2]), "r"(a[3]), "r"(b0), "r"(b1));
}
__device__ __forceinline__ void lds64(uint32_t a, uint32_t& x, uint32_t& y) {
    asm volatile("ld.shared.v2.b32 {%0,%1}, [%2];" : "=r"(x), "=r"(y) : "r"(a));
}
__device__ __forceinline__ void sts128(uint32_t a, uint32_t x, uint32_t y, uint32_t z, uint32_t w) {
    asm volatile("st.shared.v4.b32 [%0], {%1,%2,%3,%4};"
                 :: "r"(a), "r"(x), "r"(y), "r"(z), "r"(w) : "memory");
}

// One "cell" = 32 bytes of a 128x32 tile: row r (0..127), 8-col group grp (0..3).
struct Cell { float4 lo, hi; };

__device__ __forceinline__ Cell ldCell(const float* __restrict__ gp, int r, int grp) {
    Cell c;
    const float4* p = reinterpret_cast<const float4*>(gp + (size_t)r * D_ + grp * 8);
    c.lo = __ldg(p); c.hi = __ldg(p + 1);
    return c;
}

// Physical layout of a 128x32 tile (128B per row, 16 x 8B slots):
//   logical k-pair q = (kk, t) holding cols (kk*8+t, kk*8+t+4)
//   stored at slot (kk ^ (r&3))*4 + t   (8 bytes per slot)
// Fragment load for (kk, t): half-warp lanes (4 row-classes x 4 t) tile all
// 16 slots bijectively -> conflict-free LDS.64.
// STS: thread (r = tid>>2, grp = tid&3) writes its 32B region as two STS.128;
// even/odd lanes issue the two halves in opposite order so each 8-lane store
// phase covers 8 distinct 16B slots -> conflict-free STS.128.
__device__ __forceinline__ void stCell(uint32_t tile, int r, int grp, const Cell& c, int par) {
    uint32_t base = tile + (uint32_t)(r * 128) + (uint32_t)(((grp ^ (r & 3)) & 3) * 32);
    // half0 (slots t=0,1): cols (grp*8+0, +4, +1, +5); half1: (+2, +6, +3, +7)
    uint32_t h0x = f2tf32(c.lo.x), h0y = f2tf32(c.hi.x), h0z = f2tf32(c.lo.y), h0w = f2tf32(c.hi.y);
    uint32_t h1x = f2tf32(c.lo.z), h1y = f2tf32(c.hi.z), h1z = f2tf32(c.lo.w), h1w = f2tf32(c.hi.w);
    uint32_t aFirst  = base + (uint32_t)(par << 4);
    uint32_t aSecond = base + (uint32_t)(16 - (par << 4));
    // data routed so half0 always lands at base+0, half1 at base+16
    uint32_t fx = par ? h1x : h0x, fy = par ? h1y : h0y, fz = par ? h1z : h0z, fw = par ? h1w : h0w;
    uint32_t sx = par ? h0x : h1x, sy = par ? h0y : h1y, sz = par ? h0z : h1z, sw = par ? h0w : h1w;
    sts128(aFirst,  fx, fy, fz, fw);
    sts128(aSecond, sx, sy, sz, sw);
}

// ---------------------------------------------------------------------------
// Kernel 1: gate path.
//   h = relu(old_x @ W1^T + b1) + old_x ; logit = h . W2 + b2 ; g = sigmoid
// 512 threads, warp tile 32x32, N looped over 4 tiles, double-buffered smem,
// one __syncthreads per chunk.
// ---------------------------------------------------------------------------
#define K1_STAGE 32768
#define K1_SMEM  (K1_STAGE * 2 + 512)

__global__ void __launch_bounds__(512, 1) k1_gate(
    const float* __restrict__ old_x, const int* __restrict__ lang,
    const float* __restrict__ gW1,  const float* __restrict__ gb1,
    const float* __restrict__ gW2,  const float* __restrict__ gb2)
{
    extern __shared__ __align__(16) char dsm[];
    const uint32_t sb = smem_u32(dsm);
    const uint32_t A0 = sb, B0 = sb + 16384;
    float* logits = reinterpret_cast<float*>(dsm + K1_STAGE * 2);

    const int tid  = threadIdx.x;
    const int wid  = tid >> 5, lane = tid & 31;
    const int g    = lane >> 2, t = lane & 3;
    const int wm   = wid & 3,  wn  = wid >> 2;       // 4x4 warp grid
    const int cr   = tid >> 2, cg  = tid & 3;        // cell coords
    const int par  = tid & 1;

    const int rt   = blockIdx.x;
    const int row0 = rt * 128;
    const int lg   = lang[rt >> 4];

    const float* W1l = gW1 + (size_t)lg * D_ * D_;
    const float* b1l = gb1 + lg * D_;
    const float* W2l = gW2 + lg * D_;
    const float* oxA = old_x + (size_t)row0 * D_;

    if (tid < 128) logits[tid] = 0.f;

    const uint32_t aB = A0 + (uint32_t)((wm * 32 + g) * 128);
    const uint32_t bB = B0 + (uint32_t)((wn * 32 + g) * 128);
    const int g3 = g & 3;

    float part[2][2] = {{0.f, 0.f}, {0.f, 0.f}};

    for (int nt = 0; nt < 4; nt++) {
        const float* pB = W1l + (size_t)(nt * 128) * D_;
        float cc[2][4][4];
        #pragma unroll
        for (int mi = 0; mi < 2; mi++)
            #pragma unroll
            for (int ni = 0; ni < 4; ni++)
                #pragma unroll
                for (int r = 0; r < 4; r++) cc[mi][ni][r] = 0.f;

        Cell ca = ldCell(oxA, cr, cg);
        Cell cb = ldCell(pB,  cr, cg);
        __syncthreads();                       // stage 0 free (prev nt drained)
        stCell(A0, cr, cg, ca, par);
        stCell(B0, cr, cg, cb, par);

        #pragma unroll 1
        for (int c = 0; c < 16; c++) {
            __syncthreads();
            if (c < 15) {
                int k0 = (c + 1) * 32;
                ca = ldCell(oxA + k0, cr, cg);
                cb = ldCell(pB  + k0, cr, cg);
            }
            const uint32_t so = (uint32_t)(c & 1) * K1_STAGE;
            #pragma unroll
            for (int kk = 0; kk < 4; kk++) {
                const uint32_t co = (uint32_t)(((kk ^ g3) * 32) + t * 8);
                uint32_t a[2][4];
                lds64(aB + so + co,        a[0][0], a[0][2]);
                lds64(aB + so + 1024 + co, a[0][1], a[0][3]);
                lds64(aB + so + 2048 + co, a[1][0], a[1][2]);
                lds64(aB + so + 3072 + co, a[1][1], a[1][3]);
                #pragma unroll
                for (int ni = 0; ni < 4; ni++) {
                    uint32_t b0, b1;
                    lds64(bB + so + (uint32_t)(ni * 1024) + co, b0, b1);
                    mma_tf32(cc[0][ni], a[0], b0, b1);
                    mma_tf32(cc[1][ni], a[1], b0, b1);
                }
            }
            if (c < 15) {
                const uint32_t so2 = (uint32_t)((c + 1) & 1) * K1_STAGE;
                stCell(A0 + so2, cr, cg, ca, par);
                stCell(B0 + so2, cr, cg, cb, par);
            }
        }

        // Fused epilogue: relu(+b1) + old_x, dot W2, accumulate per-row partials.
        #pragma unroll
        for (int mi = 0; mi < 2; mi++) {
            #pragma unroll
            for (int h = 0; h < 2; h++) {
                const int r    = wm * 32 + mi * 16 + h * 8 + g;
                const int grow = row0 + r;
                const float* oxr = old_x + (size_t)grow * D_;
                float acc = 0.f;
                #pragma unroll
                for (int ni = 0; ni < 4; ni++) {
                    const int e = nt * 128 + wn * 32 + ni * 8 + 2 * t;
                    float2 b1v = *reinterpret_cast<const float2*>(b1l + e);
                    float2 w2v = *reinterpret_cast<const float2*>(W2l + e);
                    float2 oxv = *reinterpret_cast<const float2*>(oxr + e);
                    float u0 = fmaxf(cc[mi][ni][2 * h]     + b1v.x, 0.f) + oxv.x;
                    float u1 = fmaxf(cc[mi][ni][2 * h + 1] + b1v.y, 0.f) + oxv.y;
                    acc += u0 * w2v.x + u1 * w2v.y;
                }
                part[mi][h] += acc;
            }
        }
    }

    #pragma unroll
    for (int mi = 0; mi < 2; mi++)
        #pragma unroll
        for (int h = 0; h < 2; h++)
            atomicAdd(&logits[wm * 32 + mi * 16 + h * 8 + g], part[mi][h]);

    __syncthreads();
    if (tid < 128) {
        float z = logits[tid] + gb2[lg];
        g_gate[row0 + tid] = 1.f / (1.f + expf(-z));
    }
}

// ---------------------------------------------------------------------------
// Kernel 2: dual-GEMM mix.
//   out = (x@Ws^T) * (1-g) + (x@Wl^T) * g
// 512 threads, warp tile 32x32 per GEMM, shared A fragments, one K loop,
// one __syncthreads per chunk. Grid: nt fast so 4 CTAs share an x slab (L2).
// ---------------------------------------------------------------------------
#define K2_STAGE 49152
#define K2_SMEM  (K2_STAGE * 2)

__global__ void __launch_bounds__(512, 1) k2_mix(
    const float* __restrict__ x,      const int* __restrict__ lang,
    const float* __restrict__ shareW, const float* __restrict__ langsW,
    float* __restrict__ out)
{
    extern __shared__ __align__(16) char dsm[];
    const uint32_t sb = smem_u32(dsm);
    const uint32_t A0 = sb, BS0 = sb + 16384, BL0 = sb + 32768;

    const int tid  = threadIdx.x;
    const int wid  = tid >> 5, lane = tid & 31;
    const int g    = lane >> 2, t = lane & 3;
    const int wm   = wid & 3,  wn  = wid >> 2;
    const int cr   = tid >> 2, cg  = tid & 3;
    const int par  = tid & 1;

    const int nt   = blockIdx.x;           // fast: 4 CTAs share one x slab
    const int rt   = blockIdx.y;
    const int row0 = rt * 128;
    const int n0   = nt * 128;
    const int lg   = lang[rt >> 4];

    const float* xA = x + (size_t)row0 * D_;
    const float* pS = shareW + (size_t)n0 * D_;
    const float* pL = langsW + (size_t)lg * D_ * D_ + (size_t)n0 * D_;

    float cs[2][4][4], cl[2][4][4];
    #pragma unroll
    for (int mi = 0; mi < 2; mi++)
        #pragma unroll
        for (int ni = 0; ni < 4; ni++)
            #pragma unroll
            for (int r = 0; r < 4; r++) { cs[mi][ni][r] = 0.f; cl[mi][ni][r] = 0.f; }

    Cell ca = ldCell(xA, cr, cg);
    Cell cS = ldCell(pS, cr, cg);
    Cell cL = ldCell(pL, cr, cg);
    stCell(A0,  cr, cg, ca, par);
    stCell(BS0, cr, cg, cS, par);
    stCell(BL0, cr, cg, cL, par);

    const uint32_t aB  = A0  + (uint32_t)((wm * 32 + g) * 128);
    const uint32_t bSB = BS0 + (uint32_t)((wn * 32 + g) * 128);
    const uint32_t bLB = BL0 + (uint32_t)((wn * 32 + g) * 128);
    const int g3 = g & 3;

    #pragma unroll 1
    for (int c = 0; c < 16; c++) {
        __syncthreads();
        if (c < 15) {
            int k0 = (c + 1) * 32;
            ca = ldCell(xA + k0, cr, cg);
            cS = ldCell(pS + k0, cr, cg);
            cL = ldCell(pL + k0, cr, cg);
        }
        const uint32_t so = (uint32_t)(c & 1) * K2_STAGE;
        #pragma unroll
        for (int kk = 0; kk < 4; kk++) {
            const uint32_t co = (uint32_t)(((kk ^ g3) * 32) + t * 8);
            uint32_t a[2][4];
            lds64(aB + so + co,        a[0][0], a[0][2]);
            lds64(aB + so + 1024 + co, a[0][1], a[0][3]);
            lds64(aB + so + 2048 + co, a[1][0], a[1][2]);
            lds64(aB + so + 3072 + co, a[1][1], a[1][3]);
            #pragma unroll
            for (int ni = 0; ni < 4; ni++) {
                uint32_t s0, s1, l0, l1;
                lds64(bSB + so + (uint32_t)(ni * 1024) + co, s0, s1);
                lds64(bLB + so + (uint32_t)(ni * 1024) + co, l0, l1);
                mma_tf32(cs[0][ni], a[0], s0, s1);
                mma_tf32(cs[1][ni], a[1], s0, s1);
                mma_tf32(cl[0][ni], a[0], l0, l1);
                mma_tf32(cl[1][ni], a[1], l0, l1);
            }
        }
        if (c < 15) {
            const uint32_t so2 = (uint32_t)((c + 1) & 1) * K2_STAGE;
            stCell(A0  + so2, cr, cg, ca, par);
            stCell(BS0 + so2, cr, cg, cS, par);
            stCell(BL0 + so2, cr, cg, cL, par);
        }
    }

    // Epilogue: blend with gate, float2 stores.
    #pragma unroll
    for (int mi = 0; mi < 2; mi++) {
        #pragma unroll
        for (int h = 0; h < 2; h++) {
            const int r    = wm * 32 + mi * 16 + h * 8 + g;
            const int grow = row0 + r;
            const float gv  = g_gate[grow];
            const float ngv = 1.f - gv;
            float* orow = out + (size_t)grow * D_ + n0 + wn * 32;
            #pragma unroll
            for (int ni = 0; ni < 4; ni++) {
                float2 v;
                v.x = cs[mi][ni][2 * h]     * ngv + cl[mi][ni][2 * h]     * gv;
                v.y = cs[mi][ni][2 * h + 1] * ngv + cl[mi][ni][2 * h + 1] * gv;
                *reinterpret_cast<float2*>(orow + ni * 8 + 2 * t) = v;
            }
        }
    }
}

// ---------------------------------------------------------------------------
// launch
// ---------------------------------------------------------------------------
extern "C" void kernel_launch(void* const* d_in, const int* in_sizes, int n_in,
                              void* d_out, int out_size)
{
    const float* old_x  = (const float*)d_in[0];
    const float* x      = (const float*)d_in[1];
    const int*   lang   = (const int*)  d_in[2];
    const float* shareW = (const float*)d_in[3];
    const float* langsW = (const float*)d_in[4];
    const float* gW1    = (const float*)d_in[5];
    const float* gb1    = (const float*)d_in[6];
    const float* gW2    = (const float*)d_in[7];
    const float* gb2    = (const float*)d_in[8];
    float* out = (float*)d_out;

    cudaFuncSetAttribute(k1_gate, cudaFuncAttributeMaxDynamicSharedMemorySize, K1_SMEM);
    cudaFuncSetAttribute(k2_mix,  cudaFuncAttributeMaxDynamicSharedMemorySize, K2_SMEM);

    k1_gate<<<M_TOTAL / 128, 512, K1_SMEM>>>(old_x, lang, gW1, gb1, gW2, gb2);
    k2_mix<<<dim3(D_ / 128, M_TOTAL / 128), 512, K2_SMEM>>>(x, lang, shareW, langsW, out);
}